// round 8
// baseline (speedup 1.0000x reference)
#include <cuda_runtime.h>
#include <cuda_bf16.h>
#include <math.h>

#define Hdim 256
#define Wdim 256
#define HW   65536
#define CC   12
#define BB   8
#define BC   96
#define SENT 600        // sentinel: 600^2 = 360000 > max real d^2 (130050)

// Scratch (device globals; no allocation allowed)
__device__ unsigned short g_vU[BC * HW]; // up-scan:  dist-to-zero above | (fg<<15)
__device__ unsigned short g_vD[BC * HW]; // down-scan: dist-to-zero below
__device__ float g_dt  [BC * HW];        // signed distance dt = neg - pos
__device__ int   g_hasfg[BC];
__device__ float g_minmax[BC * 2];       // (min, max) per bc  -- atomic
__device__ float g_dsum  [BC * 2];       // (sum d, sum d^2)    -- atomic
__device__ float g_sums  [BC * 3];       // (sum p*d, sum p, sum p^2)
__device__ unsigned g_ctr;               // k_sums completion counter

__device__ __forceinline__ float atomicMinFloat(float* a, float v) {
    return (v >= 0.0f)
        ? __int_as_float(atomicMin((int*)a, __float_as_int(v)))
        : __uint_as_float(atomicMax((unsigned*)a, __float_as_uint(v)));
}
__device__ __forceinline__ float atomicMaxFloat(float* a, float v) {
    return (v >= 0.0f)
        ? __int_as_float(atomicMax((int*)a, __float_as_int(v)))
        : __uint_as_float(atomicMin((unsigned*)a, __float_as_uint(v)));
}

// ---------------------------------------------------------------------------
// K1: vertical 1D distance per column, split into TWO INDEPENDENT blocks
// per (b,c): even block = down-scan (distance to nearest zero at-or-above,
// plus fg flag, plus hasfg + accumulator init), odd block = up-scan
// (distance to nearest zero at-or-below). k_hmin combines with min().
// Doubles block count (192 -> full SM coverage) and halves the serial
// chain per block vs the fused two-pass version.
// Per pixel/class the relevant "zero" is: fg pixel -> nearest bg,
// bg pixel -> nearest fg (the only transform that pixel needs).
// ---------------------------------------------------------------------------
__global__ void __launch_bounds__(256) k_vert(const int* __restrict__ targets) {
    const int bc  = blockIdx.x >> 1;
    const int dir = blockIdx.x & 1;
    const int b   = bc / CC, c = bc % CC;
    const int w   = threadIdx.x;
    const int* tb = targets + b * HW;

    if (blockIdx.x == 0) {
        if (w < BC) {
            g_minmax[w * 2]     =  1e30f;
            g_minmax[w * 2 + 1] = -1e30f;
        }
        if (w < BC * 2) g_dsum[w] = 0.0f;
        for (int k = w; k < BC * 3; k += 256) g_sums[k] = 0.0f;
        if (w == 0) g_ctr = 0u;
    }

    if (dir == 0) {
        unsigned short* V = g_vU + bc * HW;
        int upP = -100000;   // last bg row (zero of m)
        int upN = -100000;   // last fg row (zero of ~m)
        int anyfg = 0;
        #pragma unroll 8
        for (int h = 0; h < Hdim; ++h) {
            const int fg = (tb[h * Wdim + w] == c);
            anyfg |= fg;
            if (!fg) upP = h;
            else     upN = h;
            const int d = fg ? min(h - upP, SENT) : min(h - upN, SENT);
            V[h * Wdim + w] = (unsigned short)(d | (fg << 15));
        }
        const int blkfg = __syncthreads_or(anyfg);
        if (w == 0) g_hasfg[bc] = blkfg;
    } else {
        unsigned short* V = g_vD + bc * HW;
        int dnP = 100000, dnN = 100000;
        #pragma unroll 8
        for (int h = Hdim - 1; h >= 0; --h) {
            const int fg = (tb[h * Wdim + w] == c);
            if (!fg) dnP = h;
            else     dnN = h;
            const int d = fg ? min(dnP - h, SENT) : min(dnN - h, SENT);
            V[h * Wdim + w] = (unsigned short)d;
        }
    }
}

// ---------------------------------------------------------------------------
// K2: horizontal exact min-plus via outward search with early exit.
//   d2(j) = min_k (j-k)^2 + g2[k];  stop when r^2 >= best (exact).
// Vertical g rebuilt at fill: g = min(up, down); fg from up's bit 15.
//   shP[k] = fg_k ? g_k^2 : 0;  shN[k] = fg_k ? 0 : g_k^2;  best = g_j^2.
// Fused block reduction: per-(b,c) min, max, sum(dt), sum(dt^2).
// ---------------------------------------------------------------------------
__global__ void __launch_bounds__(256) k_hmin() {
    const int row = blockIdx.x;            // bc*H + h
    const int bc  = row >> 8;
    const int j   = threadIdx.x;

    __shared__ float shP[768];             // [256..512) real, pads = +INF
    __shared__ float shN[768];
    const unsigned vu = g_vU[row * Wdim + j];
    const unsigned vd = g_vD[row * Wdim + j];
    const int   fgi = (int)(vu >> 15);
    const float d   = (float)min((int)(vu & 0x7fffu), (int)vd);
    const float fsq = d * d;
    shP[j]       = 1.0e9f;  shN[j]       = 1.0e9f;
    shP[256 + j] = fgi ? fsq : 0.0f;
    shN[256 + j] = fgi ? 0.0f : fsq;
    shP[512 + j] = 1.0e9f;  shN[512 + j] = 1.0e9f;
    const int hf = g_hasfg[bc];
    __syncthreads();

    const float* s = (fgi ? shP : shN) + 256 + j;
    float best = fsq;                      // own value in the selected array
    float rr = 1.0f, dr = 3.0f;            // rr = r^2, incremental
    #pragma unroll 1
    for (int r = 1; r < 256; ++r) {
        if (rr >= best) break;
        best = fminf(best, rr + s[-r]);
        best = fminf(best, rr + s[ r]);
        rr += dr; dr += 2.0f;
    }
    float dt = fgi ? -sqrtf(best) : sqrtf(best);
    if (!hf) dt = 0.0f;
    g_dt[row * Wdim + j] = dt;

    // fused block reduction: min, max, sum, sum of squares -> 4 atomics
    float mn = dt, mx = dt, sd = dt, sd2 = dt * dt;
    #pragma unroll
    for (int o = 16; o; o >>= 1) {
        mn  = fminf(mn, __shfl_xor_sync(0xffffffffu, mn, o));
        mx  = fmaxf(mx, __shfl_xor_sync(0xffffffffu, mx, o));
        sd  += __shfl_xor_sync(0xffffffffu, sd,  o);
        sd2 += __shfl_xor_sync(0xffffffffu, sd2, o);
    }
    __shared__ float red[4][8];
    const int wid = j >> 5, lane = j & 31;
    if (lane == 0) { red[0][wid] = mn; red[1][wid] = mx; red[2][wid] = sd; red[3][wid] = sd2; }
    __syncthreads();
    if (j == 0) {
        mn = red[0][0]; mx = red[1][0]; sd = red[2][0]; sd2 = red[3][0];
        #pragma unroll
        for (int i = 1; i < 8; ++i) {
            mn  = fminf(mn, red[0][i]);
            mx  = fmaxf(mx, red[1][i]);
            sd  += red[2][i];
            sd2 += red[3][i];
        }
        atomicMinFloat(&g_minmax[bc * 2],     mn);
        atomicMaxFloat(&g_minmax[bc * 2 + 1], mx);
        atomicAdd(&g_dsum[bc * 2],     sd);
        atomicAdd(&g_dsum[bc * 2 + 1], sd2);
    }
}

// ---------------------------------------------------------------------------
// K3: fused softmax + raw dice moments + (last block) final loss.
//   Spd = sum p*dt,  Sp = sum p,  Sp2 = sum p^2   per class (no normalize).
// Grid: (b, 32 row-groups) = 256 blocks; thread handles one column x 8 rows.
// Last finishing block reconstructs normalized sums and writes the loss:
//   inter = inv*(Spd - dmin*Sp)
//   D2    = inv^2*(Sd2 - 2*dmin*Sd + N*dmin^2)
// ---------------------------------------------------------------------------
__global__ void __launch_bounds__(256, 3) k_sums(const float* __restrict__ logits,
                                                 float* __restrict__ out) {
    const int blk = blockIdx.x;            // b*32 + rowgroup
    const int b   = blk >> 5;
    const int h0  = (blk & 31) * 8;
    const int w   = threadIdx.x;

    float aI[CC], aS[CC], aP2[CC];
    #pragma unroll
    for (int c = 0; c < CC; ++c) { aI[c] = 0.0f; aS[c] = 0.0f; aP2[c] = 0.0f; }

    const int boffL = b * CC * HW;
    for (int r = 0; r < 8; ++r) {
        const int pix = (h0 + r) * Wdim + w;
        float l[CC];
        float mxl = -1e30f;
        #pragma unroll
        for (int c = 0; c < CC; ++c) {
            l[c] = logits[boffL + c * HW + pix];
            mxl = fmaxf(mxl, l[c]);
        }
        float s = 0.0f;
        #pragma unroll
        for (int c = 0; c < CC; ++c) { l[c] = __expf(l[c] - mxl); s += l[c]; }
        const float rs = 1.0f / s;
        #pragma unroll
        for (int c = 0; c < CC; ++c) {
            const float p = l[c] * rs;
            const float dd = g_dt[boffL + c * HW + pix];
            aI [c] = fmaf(p, dd, aI [c]);
            aS [c] += p;
            aP2[c] = fmaf(p, p, aP2[c]);
        }
    }

    #pragma unroll
    for (int c = 0; c < CC; ++c) {
        #pragma unroll
        for (int o = 16; o; o >>= 1) {
            aI [c] += __shfl_xor_sync(0xffffffffu, aI [c], o);
            aS [c] += __shfl_xor_sync(0xffffffffu, aS [c], o);
            aP2[c] += __shfl_xor_sync(0xffffffffu, aP2[c], o);
        }
    }
    __shared__ float sred[36][8];
    const int lane = w & 31, wi = w >> 5;
    if (lane == 0) {
        #pragma unroll
        for (int c = 0; c < CC; ++c) {
            sred[c * 3 + 0][wi] = aI [c];
            sred[c * 3 + 1][wi] = aS [c];
            sred[c * 3 + 2][wi] = aP2[c];
        }
    }
    __syncthreads();
    if (w < 36) {
        float acc = 0.0f;
        #pragma unroll
        for (int i = 0; i < 8; ++i) acc += sred[w][i];
        const int c    = w / 3;
        const int comp = w - c * 3;
        atomicAdd(&g_sums[(b * CC + c) * 3 + comp], acc);
    }

    // ---- last-block-done: compute the final loss, no extra launch ----
    __threadfence();
    __shared__ unsigned done;
    if (w == 0) done = atomicAdd(&g_ctr, 1u);
    __syncthreads();
    if (done == gridDim.x - 1) {
        __threadfence();
        __shared__ float sfin[BC];
        if (w < BC) {
            const float dmin = g_minmax[w * 2];
            const float dmax = g_minmax[w * 2 + 1];
            const float inv  = 1.0f / (dmax - dmin + 1e-8f);
            const float Spd  = g_sums[w * 3];
            const float Sp   = g_sums[w * 3 + 1];
            const float Sp2  = g_sums[w * 3 + 2];
            const float Sd   = g_dsum[w * 2];
            const float Sd2  = g_dsum[w * 2 + 1];
            const float I  = inv * (Spd - dmin * Sp);
            const float D2 = inv * inv * (Sd2 - 2.0f * dmin * Sd + 65536.0f * dmin * dmin);
            sfin[w] = 1.0f - 2.0f * I / (Sp2 + D2 + 1e-6f);
        }
        __syncthreads();
        if (w == 0) {
            float acc = 0.0f;
            #pragma unroll
            for (int i = 0; i < BC; ++i) acc += sfin[i];
            out[0] = acc / (float)BC;
        }
    }
}

extern "C" void kernel_launch(void* const* d_in, const int* in_sizes, int n_in,
                              void* d_out, int out_size) {
    const float* logits  = (const float*)d_in[0];
    const int*   targets = (const int*)d_in[1];
    float* out = (float*)d_out;

    k_vert <<<BC * 2, 256>>>(targets);
    k_hmin <<<BC * Hdim, 256>>>();
    k_sums <<<BB * 32, 256>>>(logits, out);
}

// round 9
// speedup vs baseline: 1.0199x; 1.0199x over previous
#include <cuda_runtime.h>
#include <cuda_bf16.h>
#include <math.h>

#define Hdim 256
#define Wdim 256
#define HW   65536
#define CC   12
#define BB   8
#define BC   96
#define SENT 600        // sentinel: 600^2 = 360000 > max real d^2 (130050)

// Scratch (device globals; no allocation allowed)
__device__ unsigned short g_vU[BC * HW]; // up-scan:  dist-to-zero above | (fg<<15)
__device__ unsigned short g_vD[BC * HW]; // down-scan: dist-to-zero below
__device__ float g_dt  [BC * HW];        // signed distance dt = neg - pos
__device__ int   g_hasfg[BC];
__device__ float g_minmax[BC * 2];       // (min, max) per bc  -- atomic
__device__ float g_dsum  [BC * 2];       // (sum d, sum d^2)    -- atomic
__device__ float g_sums  [BC * 3];       // (sum p*d, sum p, sum p^2)
__device__ unsigned g_ctr;               // k_sums completion counter

__device__ __forceinline__ float atomicMinFloat(float* a, float v) {
    return (v >= 0.0f)
        ? __int_as_float(atomicMin((int*)a, __float_as_int(v)))
        : __uint_as_float(atomicMax((unsigned*)a, __float_as_uint(v)));
}
__device__ __forceinline__ float atomicMaxFloat(float* a, float v) {
    return (v >= 0.0f)
        ? __int_as_float(atomicMax((int*)a, __float_as_int(v)))
        : __uint_as_float(atomicMin((unsigned*)a, __float_as_uint(v)));
}

// ---------------------------------------------------------------------------
// K1: vertical 1D distance per column, split into TWO INDEPENDENT blocks
// per (b,c): even block = down-scan (dist to nearest zero at-or-above + fg
// flag + hasfg + accumulator init), odd block = up-scan (dist to nearest
// zero at-or-below). k_hmin combines with min(). Unroll 16 for load MLP.
// ---------------------------------------------------------------------------
__global__ void __launch_bounds__(256) k_vert(const int* __restrict__ targets) {
    const int bc  = blockIdx.x >> 1;
    const int dir = blockIdx.x & 1;
    const int b   = bc / CC, c = bc % CC;
    const int w   = threadIdx.x;
    const int* tb = targets + b * HW;

    if (blockIdx.x == 0) {
        if (w < BC) {
            g_minmax[w * 2]     =  1e30f;
            g_minmax[w * 2 + 1] = -1e30f;
        }
        if (w < BC * 2) g_dsum[w] = 0.0f;
        for (int k = w; k < BC * 3; k += 256) g_sums[k] = 0.0f;
        if (w == 0) g_ctr = 0u;
    }

    if (dir == 0) {
        unsigned short* V = g_vU + bc * HW;
        int upP = -100000;   // last bg row (zero of m)
        int upN = -100000;   // last fg row (zero of ~m)
        int anyfg = 0;
        #pragma unroll 16
        for (int h = 0; h < Hdim; ++h) {
            const int fg = (tb[h * Wdim + w] == c);
            anyfg |= fg;
            if (!fg) upP = h;
            else     upN = h;
            const int d = fg ? min(h - upP, SENT) : min(h - upN, SENT);
            V[h * Wdim + w] = (unsigned short)(d | (fg << 15));
        }
        const int blkfg = __syncthreads_or(anyfg);
        if (w == 0) g_hasfg[bc] = blkfg;
    } else {
        unsigned short* V = g_vD + bc * HW;
        int dnP = 100000, dnN = 100000;
        #pragma unroll 16
        for (int h = Hdim - 1; h >= 0; --h) {
            const int fg = (tb[h * Wdim + w] == c);
            if (!fg) dnP = h;
            else     dnN = h;
            const int d = fg ? min(dnP - h, SENT) : min(dnN - h, SENT);
            V[h * Wdim + w] = (unsigned short)d;
        }
    }
}

// ---------------------------------------------------------------------------
// K2: horizontal exact min-plus via outward search with early exit.
//   d2(j) = min_k (j-k)^2 + g2[k];  stop when r^2 >= best (exact).
// No padding: probe indices are CLAMPED to [0,255]. A clamped read yields
// rr + g2[edge] >= the true edge candidate (probed exactly at r=|j-edge|),
// so best never under-shoots and the result is still exact.
// Vertical g rebuilt at fill: g = min(up, down); fg from up's bit 15.
// Fused block reduction: per-(b,c) min, max, sum(dt), sum(dt^2).
// ---------------------------------------------------------------------------
__global__ void __launch_bounds__(256) k_hmin() {
    const int row = blockIdx.x;            // bc*H + h
    const int bc  = row >> 8;
    const int j   = threadIdx.x;

    __shared__ float shP[256];
    __shared__ float shN[256];
    const unsigned vu = g_vU[row * Wdim + j];
    const unsigned vd = g_vD[row * Wdim + j];
    const int   fgi = (int)(vu >> 15);
    const float d   = (float)min((int)(vu & 0x7fffu), (int)vd);
    const float fsq = d * d;
    shP[j] = fgi ? fsq : 0.0f;
    shN[j] = fgi ? 0.0f : fsq;
    const int hf = g_hasfg[bc];
    __syncthreads();

    const float* s = fgi ? shP : shN;
    float best = fsq;                      // own value in the selected array
    float rr = 1.0f, dr = 3.0f;            // rr = r^2, incremental
    #pragma unroll 1
    for (int r = 1; r < 256; ++r) {
        if (rr >= best) break;
        const int kl = max(j - r, 0);
        const int kr = min(j + r, 255);
        best = fminf(best, rr + s[kl]);
        best = fminf(best, rr + s[kr]);
        rr += dr; dr += 2.0f;
    }
    float dt = fgi ? -sqrtf(best) : sqrtf(best);
    if (!hf) dt = 0.0f;
    g_dt[row * Wdim + j] = dt;

    // fused block reduction: min, max, sum, sum of squares -> 4 atomics
    float mn = dt, mx = dt, sd = dt, sd2 = dt * dt;
    #pragma unroll
    for (int o = 16; o; o >>= 1) {
        mn  = fminf(mn, __shfl_xor_sync(0xffffffffu, mn, o));
        mx  = fmaxf(mx, __shfl_xor_sync(0xffffffffu, mx, o));
        sd  += __shfl_xor_sync(0xffffffffu, sd,  o);
        sd2 += __shfl_xor_sync(0xffffffffu, sd2, o);
    }
    __shared__ float red[4][8];
    const int wid = j >> 5, lane = j & 31;
    if (lane == 0) { red[0][wid] = mn; red[1][wid] = mx; red[2][wid] = sd; red[3][wid] = sd2; }
    __syncthreads();
    if (j == 0) {
        mn = red[0][0]; mx = red[1][0]; sd = red[2][0]; sd2 = red[3][0];
        #pragma unroll
        for (int i = 1; i < 8; ++i) {
            mn  = fminf(mn, red[0][i]);
            mx  = fmaxf(mx, red[1][i]);
            sd  += red[2][i];
            sd2 += red[3][i];
        }
        atomicMinFloat(&g_minmax[bc * 2],     mn);
        atomicMaxFloat(&g_minmax[bc * 2 + 1], mx);
        atomicAdd(&g_dsum[bc * 2],     sd);
        atomicAdd(&g_dsum[bc * 2 + 1], sd2);
    }
}

// ---------------------------------------------------------------------------
// K3: fused softmax + raw dice moments + (last block) final loss.
//   Spd = sum p*dt,  Sp = sum p,  Sp2 = sum p^2   per class (no normalize).
// Grid: (b, 64 row-groups) = 512 blocks; thread handles one column x 4 rows.
// Last finishing block reconstructs normalized sums and writes the loss:
//   inter = inv*(Spd - dmin*Sp)
//   D2    = inv^2*(Sd2 - 2*dmin*Sd + N*dmin^2)
// ---------------------------------------------------------------------------
__global__ void __launch_bounds__(256, 3) k_sums(const float* __restrict__ logits,
                                                 float* __restrict__ out) {
    const int blk = blockIdx.x;            // b*64 + rowgroup
    const int b   = blk >> 6;
    const int h0  = (blk & 63) * 4;
    const int w   = threadIdx.x;

    float aI[CC], aS[CC], aP2[CC];
    #pragma unroll
    for (int c = 0; c < CC; ++c) { aI[c] = 0.0f; aS[c] = 0.0f; aP2[c] = 0.0f; }

    const int boffL = b * CC * HW;
    for (int r = 0; r < 4; ++r) {
        const int pix = (h0 + r) * Wdim + w;
        float l[CC];
        float mxl = -1e30f;
        #pragma unroll
        for (int c = 0; c < CC; ++c) {
            l[c] = logits[boffL + c * HW + pix];
            mxl = fmaxf(mxl, l[c]);
        }
        float s = 0.0f;
        #pragma unroll
        for (int c = 0; c < CC; ++c) { l[c] = __expf(l[c] - mxl); s += l[c]; }
        const float rs = 1.0f / s;
        #pragma unroll
        for (int c = 0; c < CC; ++c) {
            const float p = l[c] * rs;
            const float dd = g_dt[boffL + c * HW + pix];
            aI [c] = fmaf(p, dd, aI [c]);
            aS [c] += p;
            aP2[c] = fmaf(p, p, aP2[c]);
        }
    }

    #pragma unroll
    for (int c = 0; c < CC; ++c) {
        #pragma unroll
        for (int o = 16; o; o >>= 1) {
            aI [c] += __shfl_xor_sync(0xffffffffu, aI [c], o);
            aS [c] += __shfl_xor_sync(0xffffffffu, aS [c], o);
            aP2[c] += __shfl_xor_sync(0xffffffffu, aP2[c], o);
        }
    }
    __shared__ float sred[36][8];
    const int lane = w & 31, wi = w >> 5;
    if (lane == 0) {
        #pragma unroll
        for (int c = 0; c < CC; ++c) {
            sred[c * 3 + 0][wi] = aI [c];
            sred[c * 3 + 1][wi] = aS [c];
            sred[c * 3 + 2][wi] = aP2[c];
        }
    }
    __syncthreads();
    if (w < 36) {
        float acc = 0.0f;
        #pragma unroll
        for (int i = 0; i < 8; ++i) acc += sred[w][i];
        const int c    = w / 3;
        const int comp = w - c * 3;
        atomicAdd(&g_sums[(b * CC + c) * 3 + comp], acc);
    }

    // ---- last-block-done: compute the final loss, no extra launch ----
    __threadfence();
    __shared__ unsigned done;
    if (w == 0) done = atomicAdd(&g_ctr, 1u);
    __syncthreads();
    if (done == gridDim.x - 1) {
        __threadfence();
        __shared__ float sfin[BC];
        if (w < BC) {
            const float dmin = g_minmax[w * 2];
            const float dmax = g_minmax[w * 2 + 1];
            const float inv  = 1.0f / (dmax - dmin + 1e-8f);
            const float Spd  = g_sums[w * 3];
            const float Sp   = g_sums[w * 3 + 1];
            const float Sp2  = g_sums[w * 3 + 2];
            const float Sd   = g_dsum[w * 2];
            const float Sd2  = g_dsum[w * 2 + 1];
            const float I  = inv * (Spd - dmin * Sp);
            const float D2 = inv * inv * (Sd2 - 2.0f * dmin * Sd + 65536.0f * dmin * dmin);
            sfin[w] = 1.0f - 2.0f * I / (Sp2 + D2 + 1e-6f);
        }
        __syncthreads();
        if (w == 0) {
            float acc = 0.0f;
            #pragma unroll
            for (int i = 0; i < BC; ++i) acc += sfin[i];
            out[0] = acc / (float)BC;
        }
    }
}

extern "C" void kernel_launch(void* const* d_in, const int* in_sizes, int n_in,
                              void* d_out, int out_size) {
    const float* logits  = (const float*)d_in[0];
    const int*   targets = (const int*)d_in[1];
    float* out = (float*)d_out;

    k_vert <<<BC * 2, 256>>>(targets);
    k_hmin <<<BC * Hdim, 256>>>();
    k_sums <<<BB * 64, 256>>>(logits, out);
}

// round 10
// speedup vs baseline: 1.4173x; 1.3896x over previous
#include <cuda_runtime.h>
#include <cuda_bf16.h>
#include <math.h>

#define Hdim 256
#define Wdim 256
#define HW   65536
#define CC   12
#define BB   8
#define BC   96
#define SENT 600        // sentinel: 600^2 = 360000 > max real d^2 (130050)

// Scratch (device globals; no allocation allowed)
__device__ unsigned short g_vU[BC * HW]; // up-scan:  dist-to-zero above | (fg<<15)
__device__ unsigned short g_vD[BC * HW]; // down-scan: dist-to-zero below
__device__ float g_dt  [BC * HW];        // signed distance dt = neg - pos
__device__ int   g_hasfg[BC];
__device__ float g_minmax[BC * 2];       // (min, max) per bc  -- atomic
__device__ float g_dsum  [BC * 2];       // (sum d, sum d^2)    -- atomic
__device__ float g_sums  [BC * 3];       // (sum p*d, sum p, sum p^2)
__device__ unsigned g_ctr;               // k_sums completion counter

__device__ __forceinline__ float atomicMinFloat(float* a, float v) {
    return (v >= 0.0f)
        ? __int_as_float(atomicMin((int*)a, __float_as_int(v)))
        : __uint_as_float(atomicMax((unsigned*)a, __float_as_uint(v)));
}
__device__ __forceinline__ float atomicMaxFloat(float* a, float v) {
    return (v >= 0.0f)
        ? __int_as_float(atomicMax((int*)a, __float_as_int(v)))
        : __uint_as_float(atomicMin((unsigned*)a, __float_as_uint(v)));
}

// ---------------------------------------------------------------------------
// K1: vertical 1D distance per column, split into TWO INDEPENDENT blocks
// per (b,c): even block = down-scan (dist to nearest zero at-or-above + fg
// flag + hasfg + accumulator init), odd block = up-scan (dist to nearest
// zero at-or-below). k_hmin combines with min(). Unroll 16 for load MLP.
// ---------------------------------------------------------------------------
__global__ void __launch_bounds__(256) k_vert(const int* __restrict__ targets) {
    const int bc  = blockIdx.x >> 1;
    const int dir = blockIdx.x & 1;
    const int b   = bc / CC, c = bc % CC;
    const int w   = threadIdx.x;
    const int* tb = targets + b * HW;

    if (blockIdx.x == 0) {
        if (w < BC) {
            g_minmax[w * 2]     =  1e30f;
            g_minmax[w * 2 + 1] = -1e30f;
        }
        if (w < BC * 2) g_dsum[w] = 0.0f;
        for (int k = w; k < BC * 3; k += 256) g_sums[k] = 0.0f;
        if (w == 0) g_ctr = 0u;
    }

    if (dir == 0) {
        unsigned short* V = g_vU + bc * HW;
        int upP = -100000;   // last bg row (zero of m)
        int upN = -100000;   // last fg row (zero of ~m)
        int anyfg = 0;
        #pragma unroll 16
        for (int h = 0; h < Hdim; ++h) {
            const int fg = (tb[h * Wdim + w] == c);
            anyfg |= fg;
            if (!fg) upP = h;
            else     upN = h;
            const int d = fg ? min(h - upP, SENT) : min(h - upN, SENT);
            V[h * Wdim + w] = (unsigned short)(d | (fg << 15));
        }
        const int blkfg = __syncthreads_or(anyfg);
        if (w == 0) g_hasfg[bc] = blkfg;
    } else {
        unsigned short* V = g_vD + bc * HW;
        int dnP = 100000, dnN = 100000;
        #pragma unroll 16
        for (int h = Hdim - 1; h >= 0; --h) {
            const int fg = (tb[h * Wdim + w] == c);
            if (!fg) dnP = h;
            else     dnN = h;
            const int d = fg ? min(dnP - h, SENT) : min(dnN - h, SENT);
            V[h * Wdim + w] = (unsigned short)d;
        }
    }
}

// ---------------------------------------------------------------------------
// K2: horizontal exact min-plus, 4 ROWS PER BLOCK (sequential per thread).
//   d2(j) = min_k (j-k)^2 + g2[k];  stop when r^2 >= best (exact).
// Probe indices clamped to [0,255] (clamped reads only over-estimate; the
// true edge candidate is probed exactly at r=|j-edge|, so still exact).
// Fill: one coalesced pass over all 4 rows (thread j loads its own pixel
// in each row -> fg/d^2 kept in registers). One __syncthreads. Each thread
// searches its column in all 4 rows, accumulating min/max/sum/sum2 in
// registers; ONE block reduction + 4 atomics per 4 rows.
// ---------------------------------------------------------------------------
__global__ void __launch_bounds__(256) k_hmin() {
    const int row0 = blockIdx.x << 2;      // first of 4 rows (same bc: 256|4)
    const int bc   = row0 >> 8;
    const int j    = threadIdx.x;

    __shared__ float shP[4][256];
    __shared__ float shN[4][256];

    int   fgr [4];
    float fsqr[4];
    #pragma unroll
    for (int r = 0; r < 4; ++r) {
        const int gi = (row0 + r) * Wdim + j;
        const unsigned vu = g_vU[gi];
        const unsigned vd = g_vD[gi];
        const int   fgk = (int)(vu >> 15);
        const float dd  = (float)min((int)(vu & 0x7fffu), (int)vd);
        const float sq  = dd * dd;
        shP[r][j] = fgk ? sq : 0.0f;
        shN[r][j] = fgk ? 0.0f : sq;
        fgr [r] = fgk;
        fsqr[r] = sq;
    }
    const int hf = g_hasfg[bc];
    __syncthreads();

    float mn = 1e30f, mx = -1e30f, sd = 0.0f, sd2 = 0.0f;
    #pragma unroll
    for (int r = 0; r < 4; ++r) {
        const float* s = fgr[r] ? shP[r] : shN[r];
        float best = fsqr[r];
        float rr = 1.0f, dr = 3.0f;
        #pragma unroll 1
        for (int t = 1; t < 256; ++t) {
            if (rr >= best) break;
            const int kl = max(j - t, 0);
            const int kr = min(j + t, 255);
            best = fminf(best, rr + s[kl]);
            best = fminf(best, rr + s[kr]);
            rr += dr; dr += 2.0f;
        }
        float dt = fgr[r] ? -sqrtf(best) : sqrtf(best);
        if (!hf) dt = 0.0f;
        g_dt[(row0 + r) * Wdim + j] = dt;
        mn  = fminf(mn, dt);
        mx  = fmaxf(mx, dt);
        sd  += dt;
        sd2 += dt * dt;
    }

    // one fused block reduction per 4 rows: min, max, sum, sum2 -> 4 atomics
    #pragma unroll
    for (int o = 16; o; o >>= 1) {
        mn  = fminf(mn, __shfl_xor_sync(0xffffffffu, mn, o));
        mx  = fmaxf(mx, __shfl_xor_sync(0xffffffffu, mx, o));
        sd  += __shfl_xor_sync(0xffffffffu, sd,  o);
        sd2 += __shfl_xor_sync(0xffffffffu, sd2, o);
    }
    __shared__ float red[4][8];
    const int wid = j >> 5, lane = j & 31;
    if (lane == 0) { red[0][wid] = mn; red[1][wid] = mx; red[2][wid] = sd; red[3][wid] = sd2; }
    __syncthreads();
    if (j == 0) {
        mn = red[0][0]; mx = red[1][0]; sd = red[2][0]; sd2 = red[3][0];
        #pragma unroll
        for (int i = 1; i < 8; ++i) {
            mn  = fminf(mn, red[0][i]);
            mx  = fmaxf(mx, red[1][i]);
            sd  += red[2][i];
            sd2 += red[3][i];
        }
        atomicMinFloat(&g_minmax[bc * 2],     mn);
        atomicMaxFloat(&g_minmax[bc * 2 + 1], mx);
        atomicAdd(&g_dsum[bc * 2],     sd);
        atomicAdd(&g_dsum[bc * 2 + 1], sd2);
    }
}

// ---------------------------------------------------------------------------
// K3: fused softmax + raw dice moments + (last block) final loss.
//   Spd = sum p*dt,  Sp = sum p,  Sp2 = sum p^2   per class (no normalize).
// Grid: (b, 64 row-groups) = 512 blocks; thread handles one column x 4 rows.
// Last finishing block reconstructs normalized sums and writes the loss:
//   inter = inv*(Spd - dmin*Sp)
//   D2    = inv^2*(Sd2 - 2*dmin*Sd + N*dmin^2)
// ---------------------------------------------------------------------------
__global__ void __launch_bounds__(256, 3) k_sums(const float* __restrict__ logits,
                                                 float* __restrict__ out) {
    const int blk = blockIdx.x;            // b*64 + rowgroup
    const int b   = blk >> 6;
    const int h0  = (blk & 63) * 4;
    const int w   = threadIdx.x;

    float aI[CC], aS[CC], aP2[CC];
    #pragma unroll
    for (int c = 0; c < CC; ++c) { aI[c] = 0.0f; aS[c] = 0.0f; aP2[c] = 0.0f; }

    const int boffL = b * CC * HW;
    for (int r = 0; r < 4; ++r) {
        const int pix = (h0 + r) * Wdim + w;
        float l[CC];
        float mxl = -1e30f;
        #pragma unroll
        for (int c = 0; c < CC; ++c) {
            l[c] = logits[boffL + c * HW + pix];
            mxl = fmaxf(mxl, l[c]);
        }
        float s = 0.0f;
        #pragma unroll
        for (int c = 0; c < CC; ++c) { l[c] = __expf(l[c] - mxl); s += l[c]; }
        const float rs = 1.0f / s;
        #pragma unroll
        for (int c = 0; c < CC; ++c) {
            const float p = l[c] * rs;
            const float dd = g_dt[boffL + c * HW + pix];
            aI [c] = fmaf(p, dd, aI [c]);
            aS [c] += p;
            aP2[c] = fmaf(p, p, aP2[c]);
        }
    }

    #pragma unroll
    for (int c = 0; c < CC; ++c) {
        #pragma unroll
        for (int o = 16; o; o >>= 1) {
            aI [c] += __shfl_xor_sync(0xffffffffu, aI [c], o);
            aS [c] += __shfl_xor_sync(0xffffffffu, aS [c], o);
            aP2[c] += __shfl_xor_sync(0xffffffffu, aP2[c], o);
        }
    }
    __shared__ float sred[36][8];
    const int lane = w & 31, wi = w >> 5;
    if (lane == 0) {
        #pragma unroll
        for (int c = 0; c < CC; ++c) {
            sred[c * 3 + 0][wi] = aI [c];
            sred[c * 3 + 1][wi] = aS [c];
            sred[c * 3 + 2][wi] = aP2[c];
        }
    }
    __syncthreads();
    if (w < 36) {
        float acc = 0.0f;
        #pragma unroll
        for (int i = 0; i < 8; ++i) acc += sred[w][i];
        const int c    = w / 3;
        const int comp = w - c * 3;
        atomicAdd(&g_sums[(b * CC + c) * 3 + comp], acc);
    }

    // ---- last-block-done: compute the final loss, no extra launch ----
    __threadfence();
    __shared__ unsigned done;
    if (w == 0) done = atomicAdd(&g_ctr, 1u);
    __syncthreads();
    if (done == gridDim.x - 1) {
        __threadfence();
        __shared__ float sfin[BC];
        if (w < BC) {
            const float dmin = g_minmax[w * 2];
            const float dmax = g_minmax[w * 2 + 1];
            const float inv  = 1.0f / (dmax - dmin + 1e-8f);
            const float Spd  = g_sums[w * 3];
            const float Sp   = g_sums[w * 3 + 1];
            const float Sp2  = g_sums[w * 3 + 2];
            const float Sd   = g_dsum[w * 2];
            const float Sd2  = g_dsum[w * 2 + 1];
            const float I  = inv * (Spd - dmin * Sp);
            const float D2 = inv * inv * (Sd2 - 2.0f * dmin * Sd + 65536.0f * dmin * dmin);
            sfin[w] = 1.0f - 2.0f * I / (Sp2 + D2 + 1e-6f);
        }
        __syncthreads();
        if (w == 0) {
            float acc = 0.0f;
            #pragma unroll
            for (int i = 0; i < BC; ++i) acc += sfin[i];
            out[0] = acc / (float)BC;
        }
    }
}

extern "C" void kernel_launch(void* const* d_in, const int* in_sizes, int n_in,
                              void* d_out, int out_size) {
    const float* logits  = (const float*)d_in[0];
    const int*   targets = (const int*)d_in[1];
    float* out = (float*)d_out;

    k_vert <<<BC * 2, 256>>>(targets);
    k_hmin <<<BC * Hdim / 4, 256>>>();
    k_sums <<<BB * 64, 256>>>(logits, out);
}